// round 3
// baseline (speedup 1.0000x reference)
#include <cuda_runtime.h>

// SimplePatchScorer: out[b, j] = dot(W, permuted_patch_row(b, j)) + bias
//   x: (512, 3, 224, 224) fp32, W: (1, 768) fp32, bias: (1,) fp32
//   out: (512, 196) fp32
//
// Per image, the scrambled flatten is flat[u], u = s*588 + v,
//   s = ph*16 + pw in [0,256), v = c*196 + hn*14 + wn in [0,588),
//   flat[u] = x[b, c, hn*16+ph, wn*16+pw]
// out[b,j] = sum_{t<768} W[t] * flat[768j + t] + bias, j in [0,196).
//
// lcm(588,768) = 37632 aligns on both s (64 values) and j (49 rows) boundaries
// => 4 independent groups per image. Block (b,g): coalesced-load the region
// (ph in [4g,4g+4), all c/hn/w) into a transposed smem buffer Y[s'][v]
// (stride 589 to kill bank conflicts), then warps compute whole output rows
// from contiguous smem reads.

#define NGROUP_U   37632      // u span per group = lcm(588,768)
#define ROWS_PER_G 49         // output rows per group
#define SVALS      64         // s' values per group
#define VLEN       588
#define VPAD       589        // padded row stride (bank stride 13, coprime w/ 32)
#define THREADS    512

__global__ __launch_bounds__(THREADS, 1)
void patch_scorer_kernel(const float* __restrict__ x,
                         const float* __restrict__ W,
                         const float* __restrict__ bias,
                         float* __restrict__ out)
{
    extern __shared__ float smem[];
    float* Y  = smem;                 // [64][589]
    float* Ws = smem + SVALS * VPAD;  // [768]

    const int tid = threadIdx.x;
    const int g   = blockIdx.x & 3;        // group 0..3
    const int b   = blockIdx.x >> 2;       // image 0..511

    const float* xb = x + (size_t)b * (3 * 224 * 224);

    // ---- load W into smem ----
    if (tid < 768 / 2) {
        // 512 threads, 768 floats: use float2 via 384 threads
        ((float2*)Ws)[tid] = ((const float2*)W)[tid];
    }

    // ---- Phase 1: coalesced stream of region -> transposed smem ----
    // Region: c in [0,3), hn in [0,14), phl in [0,4)  (ph = 4g+phl), w in [0,224)
    // Linear float4 index e4 in [0, 9408): row r = e4/56, w = 4*(e4%56)
    //   r: phl = r&3, hn = (r>>2)%14, c = r/56
    #pragma unroll 4
    for (int e4 = tid; e4 < 9408; e4 += THREADS) {
        int w4  = e4 % 56;
        int r   = e4 / 56;
        int w   = w4 << 2;
        int phl = r & 3;
        int r2  = r >> 2;
        int hn  = r2 % 14;
        int c   = r2 / 14;

        int h = hn * 16 + 4 * g + phl;
        float4 val = *(const float4*)(xb + ((size_t)c * 224 + h) * 224 + w);

        int pw = w & 15;         // 0,4,8,12 — 4 elems stay in same wn
        int wn = w >> 4;
        int sp = phl * 16 + pw;  // s' in [0,64)
        int v  = c * 196 + hn * 14 + wn;

        float* dst = &Y[sp * VPAD + v];
        dst[0 * VPAD] = val.x;
        dst[1 * VPAD] = val.y;
        dst[2 * VPAD] = val.z;
        dst[3 * VPAD] = val.w;
    }

    __syncthreads();

    // ---- Phase 2: each warp computes whole output rows ----
    const int lane = tid & 31;
    const int warp = tid >> 5;   // 16 warps
    const float bv = bias[0];

    for (int jl = warp; jl < ROWS_PER_G; jl += THREADS / 32) {
        float acc = 0.f;
        const int ubase = 768 * jl;
        #pragma unroll
        for (int k = 0; k < 24; k++) {
            int t  = lane + 32 * k;
            int uu = ubase + t;
            int sp = uu / VLEN;          // const-div -> mul/shift
            int v  = uu - sp * VLEN;
            acc += Ws[t] * Y[sp * VPAD + v];
        }
        // warp reduction
        #pragma unroll
        for (int off = 16; off; off >>= 1)
            acc += __shfl_xor_sync(0xffffffffu, acc, off);
        if (lane == 0)
            out[b * 196 + ROWS_PER_G * g + jl] = acc + bv;
    }
}

extern "C" void kernel_launch(void* const* d_in, const int* in_sizes, int n_in,
                              void* d_out, int out_size)
{
    const float* x  = (const float*)d_in[0];   // (512,3,224,224)
    const float* W  = (const float*)d_in[1];   // (1,768)
    const float* bb = (const float*)d_in[2];   // (1,)
    float* out = (float*)d_out;                // (512,196)

    const int smem_bytes = (SVALS * VPAD + 768) * sizeof(float);  // ~154 KB
    cudaFuncSetAttribute(patch_scorer_kernel,
                         cudaFuncAttributeMaxDynamicSharedMemorySize, smem_bytes);

    patch_scorer_kernel<<<512 * 4, THREADS, smem_bytes>>>(x, W, bb, out);
}